// round 14
// baseline (speedup 1.0000x reference)
#include <cuda_runtime.h>
#include <cuda_fp16.h>
#include <math.h>
#include <stdint.h>

#define PI_F 3.14159265358979f

// ---------------------------------------------------------------------------
// Scratch (__device__ globals; no runtime alloc)
// ---------------------------------------------------------------------------
__device__ __half    g_yh[25165824];      // conv output fp16, pixel-shuffled (8,48,256,256)
__device__ __half    g_h[25165824];       // REAL field h = H_s(rows) fp16
__device__ __half    g_xh[12582912];      // x transposed [b][hw][ic], fp16
__device__ __half    g_wimg[165888];      // weights fp16: 54 chunks x 3072 (LDS.128 frag layout)
__device__ float2    g_c[98304];          // per (image,row): c correction scalars

// ---------------------------------------------------------------------------
// mma.sync (fp16 in, f32 acc)
// ---------------------------------------------------------------------------
__device__ __forceinline__ void mma16816(float c[4],
                                         uint32_t a0, uint32_t a1, uint32_t a2, uint32_t a3,
                                         uint32_t b0, uint32_t b1) {
    asm volatile(
        "mma.sync.aligned.m16n8k16.row.col.f32.f16.f16.f32 "
        "{%0,%1,%2,%3}, {%4,%5,%6,%7}, {%8,%9}, {%0,%1,%2,%3};"
        : "+f"(c[0]), "+f"(c[1]), "+f"(c[2]), "+f"(c[3])
        : "r"(a0), "r"(a1), "r"(a2), "r"(a3), "r"(b0), "r"(b1));
}

__device__ __forceinline__ uint32_t smem_u32(const void* p) {
    uint32_t a;
    asm("{ .reg .u64 t; cvta.to.shared.u64 t, %1; cvt.u32.u64 %0, t; }" : "=r"(a) : "l"(p));
    return a;
}
__device__ __forceinline__ void cp_async16(uint32_t dst, const void* src) {
    asm volatile("cp.async.cg.shared.global [%0], [%1], 16;" :: "r"(dst), "l"(src));
}
__device__ __forceinline__ void cp_async16z(uint32_t dst, const void* src, bool inb) {
    int sz = inb ? 16 : 0;
    asm volatile("cp.async.cg.shared.global [%0], [%1], 16, %2;" :: "r"(dst), "l"(src), "r"(sz));
}
__device__ __forceinline__ void cp_commit() { asm volatile("cp.async.commit_group;"); }
__device__ __forceinline__ void cp_wait0()  { asm volatile("cp.async.wait_group 0;"); }
__device__ __forceinline__ void cp_wait1()  { asm volatile("cp.async.wait_group 1;"); }
__device__ __forceinline__ void cp_wait2()  { asm volatile("cp.async.wait_group 2;"); }

__device__ __forceinline__ uint32_t pack_h2(float a, float b) {
    uint32_t r;
    asm("cvt.rn.f16x2.f32 %0, %1, %2;" : "=r"(r) : "f"(b), "f"(a));
    return r;
}
__device__ __forceinline__ float2 unpack_h2(uint32_t v) {
    __half2 h = *reinterpret_cast<const __half2*>(&v);
    return __half22float2(h);
}
__device__ __forceinline__ float fsqrt_ap(float x) {
    float r;
    asm("sqrt.approx.f32 %0, %1;" : "=f"(r) : "f"(x));
    return r;
}

// ---------------------------------------------------------------------------
// Warp-FFT machinery
// ---------------------------------------------------------------------------
__device__ __forceinline__ float2 cadd(float2 a, float2 b) { return make_float2(a.x + b.x, a.y + b.y); }
__device__ __forceinline__ float2 csub(float2 a, float2 b) { return make_float2(a.x - b.x, a.y - b.y); }
__device__ __forceinline__ float2 cmul(float2 a, float2 b) {
    return make_float2(a.x * b.x - a.y * b.y, a.x * b.y + a.y * b.x);
}
__device__ __forceinline__ float2 cconj(float2 a) { return make_float2(a.x, -a.y); }
__device__ __forceinline__ float2 expi(float a) {
    float s, c;
    __sincosf(a, &s, &c);
    return make_float2(c, s);
}
__device__ __forceinline__ float2 shflxc(float2 v, int m) {
    v.x = __shfl_xor_sync(0xffffffffu, v.x, m);
    v.y = __shfl_xor_sync(0xffffffffu, v.y, m);
    return v;
}
// multiply by (-i)^s
__device__ __forceinline__ float2 rotmi(float2 v, int s) {
    s &= 3;
    if (s == 0) return v;
    if (s == 1) return make_float2(v.y, -v.x);
    if (s == 2) return make_float2(-v.x, -v.y);
    return make_float2(-v.y, v.x);
}

struct FTw2 { float2 ws0, ws1, ws2, ws3, mb; };

__device__ __forceinline__ void make_tw2(int lane, FTw2& t) {
    int brl = __brev((unsigned)lane) >> 27;
    t.ws0 = expi(-PI_F * (float)(lane & 15) / 16.0f);
    t.ws1 = expi(-PI_F * (float)(lane & 7) / 8.0f);
    const float R = 0.70710678118654752f;
    int a2 = lane & 3;
    t.ws2 = (a2 == 0) ? make_float2(1.f, 0.f)
          : (a2 == 1) ? make_float2(R, -R)
          : (a2 == 2) ? make_float2(0.f, -1.f)
                      : make_float2(-R, -R);
    t.ws3 = (lane & 1) ? make_float2(0.f, -1.f) : make_float2(1.f, 0.f);
    t.mb  = expi(-2.0f * PI_F * (float)brl / 256.0f);
}

__device__ __forceinline__ void xstage_fwd(float2 d[8], int S, float2 w, int lane) {
    bool hi = (lane & S) != 0;
#pragma unroll
    for (int j = 0; j < 8; j++) {
        float2 o = shflxc(d[j], S);
        d[j] = hi ? cmul(csub(o, d[j]), w) : cadd(d[j], o);
    }
}
__device__ __forceinline__ void xstage_unity(float2 d[8], int lane) {
    bool hi = (lane & 1) != 0;
#pragma unroll
    for (int j = 0; j < 8; j++) {
        float2 o = shflxc(d[j], 1);
        d[j] = hi ? csub(o, d[j]) : cadd(d[j], o);
    }
}
__device__ __forceinline__ void xstage_inv(float2 d[8], int S, float2 wc, int lane) {
    bool hi = (lane & S) != 0;
#pragma unroll
    for (int j = 0; j < 8; j++) {
        float2 pre = hi ? cmul(d[j], wc) : d[j];
        float2 o = shflxc(pre, S);
        d[j] = hi ? csub(o, pre) : cadd(pre, o);
    }
}

__device__ __forceinline__ void fftH_front(float2 d[8], const FTw2& t, int lane) {
    xstage_fwd(d, 16, t.ws0, lane);
    xstage_fwd(d, 8,  t.ws1, lane);
    xstage_fwd(d, 4,  t.ws2, lane);
    xstage_fwd(d, 2,  t.ws3, lane);
    xstage_unity(d, lane);
    {
        float2 m = t.mb;
        d[1] = cmul(d[1], m);
#pragma unroll
        for (int j = 2; j < 8; j++) { m = cmul(m, t.mb); d[j] = cmul(d[j], m); }
    }
    const float R = 0.70710678118654752f;
    const float2 W81 = make_float2(R, -R);
    const float2 W83 = make_float2(-R, -R);
    {
        float2 u, v, tt;
        u = d[0]; v = d[4]; d[0] = cadd(u, v); d[4] = csub(u, v);
        u = d[1]; v = d[5]; d[1] = cadd(u, v); d[5] = cmul(csub(u, v), W81);
        u = d[2]; v = d[6]; d[2] = cadd(u, v); tt = csub(u, v); d[6] = make_float2(tt.y, -tt.x);
        u = d[3]; v = d[7]; d[3] = cadd(u, v); d[7] = cmul(csub(u, v), W83);
    }
#pragma unroll
    for (int gg = 0; gg < 8; gg += 4) {
        float2 u, v, tt;
        u = d[gg];     v = d[gg + 2]; d[gg] = cadd(u, v);     d[gg + 2] = csub(u, v);
        u = d[gg + 1]; v = d[gg + 3]; tt = csub(u, v);
        d[gg + 1] = cadd(u, v); d[gg + 3] = make_float2(tt.y, -tt.x);
    }
}

__device__ __forceinline__ void fftH_back(float2 d[8], const FTw2& t, int lane,
                                          bool zero192, float2* X192, float2* X64) {
    {
        float2 p = cadd(d[0], d[1]);
        float2 q = csub(d[2], d[3]);
        float2 s64 = cadd(d[2], d[3]);
        float2 r = cadd(d[4], d[5]);
        float2 s = csub(d[6], d[7]);
        if (X192 && lane == 0) { *X192 = q; *X64 = s64; }
        if (zero192 && lane == 0) q = make_float2(0.f, 0.f);
        d[0] = cadd(p, q);
        d[2] = csub(p, q);
        d[1] = make_float2(p.x + q.y, p.y - q.x);
        d[3] = make_float2(p.x - q.y, p.y + q.x);
        d[4] = cadd(r, s);
        d[6] = csub(r, s);
        d[5] = make_float2(r.x + s.y, r.y - s.x);
        d[7] = make_float2(r.x - s.y, r.y + s.x);
    }
    const float R = 0.70710678118654752f;
    const float2 W81c = make_float2(R, R);
    const float2 W83c = make_float2(-R, R);
    {
        float2 a, v;
        a = d[0]; v = d[4];                d[0] = cadd(a, v); d[4] = csub(a, v);
        a = d[1]; v = cmul(d[5], W81c);    d[1] = cadd(a, v); d[5] = csub(a, v);
        a = d[2]; { float2 bq = d[6]; v = make_float2(-bq.y, bq.x); } d[2] = cadd(a, v); d[6] = csub(a, v);
        a = d[3]; v = cmul(d[7], W83c);    d[3] = cadd(a, v); d[7] = csub(a, v);
    }
    {
        float2 mc = cconj(t.mb);
        float2 m = mc;
        d[1] = cmul(d[1], m);
#pragma unroll
        for (int j = 2; j < 8; j++) { m = cmul(m, mc); d[j] = cmul(d[j], m); }
    }
    xstage_unity(d, lane);
    xstage_inv(d, 2,  cconj(t.ws3), lane);
    xstage_inv(d, 4,  cconj(t.ws2), lane);
    xstage_inv(d, 8,  cconj(t.ws1), lane);
    xstage_inv(d, 16, cconj(t.ws0), lane);
}

__device__ __forceinline__ void apply_H(float2 d[8], const FTw2& t, int lane) {
    fftH_front(d, t, lane);
    fftH_back(d, t, lane, false, nullptr, nullptr);
}
__device__ __forceinline__ void apply_Hs_ext(float2 d[8], const FTw2& t, int lane,
                                             float2& X192, float2& X64) {
    fftH_front(d, t, lane);
    fftH_back(d, t, lane, true, &X192, &X64);
}

// ---------------------------------------------------------------------------
// Merged prep: blocks [0,648) weight fragments; [648, 12936) x transpose.
// ---------------------------------------------------------------------------
__global__ void __launch_bounds__(256) prep_kernel(const float* __restrict__ wgt,
                                                   const float* __restrict__ x) {
    __shared__ float tile[32][33];
    int t = threadIdx.x;
    int bid = blockIdx.x;
    if (bid < 648) {
        int i = bid * 256 + t;
        int e = i % 3072;
        int c = i / 3072;
        int b16 = e >> 3, h8 = e & 7;
        int tig = b16 & 3, g = (b16 >> 2) & 7, mglob = b16 >> 5;
        int ah = h8 >> 1, par = h8 & 1;
        int oc = mglob * 16 + g + 8 * (ah & 1);
        int k = ((ah >> 1) ? 8 : 0) + 2 * tig + par;
        int tap = c / 6, icg = c % 6;
        int kh = tap / 3, kw = tap % 3;
        int ic = icg * 16 + k;
        float w = wgt[((size_t)oc * 96 + ic) * 9 + kh * 3 + kw];
        g_wimg[c * 3072 + e] = __float2half(w);
        return;
    }
    int bid2 = bid - 648;
    int j = t & 31, i4 = t >> 5;
    int hw0 = (bid2 & 511) * 32;
    int ic0 = ((bid2 >> 9) % 3) * 32;
    int b = bid2 / 1536;
#pragma unroll
    for (int r = 0; r < 4; r++) {
        int ic = ic0 + i4 * 4 + r;
        tile[i4 * 4 + r][j] = x[((size_t)b * 96 + ic) * 16384 + hw0 + j];
    }
    __syncthreads();
#pragma unroll
    for (int r = 0; r < 4; r++) {
        int hwl = i4 * 4 + r;
        float v = tile[j][hwl];
        size_t idx = ((size_t)b * 16384 + hw0 + hwl) * 96 + ic0 + j;
        g_xh[idx] = __float2half(v);
    }
}

// ---------------------------------------------------------------------------
// Conv implicit GEMM + packed row-H_s epilogue.
// 4-slot weight ring, prefetch depth 2, barrier every 2 chunks.
// ---------------------------------------------------------------------------
#define XS_ELEMS 40560
#define WOFF_B 81120
#define SLOT_B 6144
#define STG_STRIDE 264
#define CONV_SMEM (WOFF_B + 4 * SLOT_B)   // 105696 >= stage 101376

__global__ void __launch_bounds__(256, 2) conv_mma_kernel() {
    extern __shared__ char sd[];
    __half* xsH = (__half*)sd;
    __half* wring = (__half*)(sd + WOFF_B);

    int t = threadIdx.x;
    int h = blockIdx.x;
    int b = blockIdx.y;
    int wid = t >> 5, lane = t & 31;
    int g = lane >> 2, tig = lane & 3;
    int ocb16 = (wid >> 2) * 6;
    int pxbase = (wid & 3) * 32;

    // G0: chunks 0,1 into slots 0,1 (768 x 16B)
    uint32_t wring_s = smem_u32(wring);
    for (int i = t; i < 768; i += 256)
        cp_async16(wring_s + i * 16, (const char*)g_wimg + i * 16);
    cp_commit();

    // G1: stage input rows with halo: [3 kh][130 ww][104 ic]
    {
        const __half* xb_h = g_xh + (size_t)b * 16384 * 96;
        uint32_t xs_s = smem_u32(xsH);
        for (int idx = t; idx < 4680; idx += 256) {
            int c16 = idx % 12;
            int ww = (idx / 12) % 130;
            int kh = idx / (12 * 130);
            int hp = h + kh - 1;
            int wp = ww - 1;
            bool inb = (hp >= 0 && hp < 128 && wp >= 0 && wp < 128);
            size_t src = inb ? (((size_t)hp * 128 + wp) * 96 + c16 * 8) : 0;
            int dst = kh * 13520 + ww * 104 + c16 * 8;
            cp_async16z(xs_s + dst * 2, xb_h + src, inb);
        }
    }
    cp_commit();
    cp_wait0();
    __syncthreads();

    float acc[6][4][4];
#pragma unroll
    for (int m = 0; m < 6; m++)
#pragma unroll
        for (int n = 0; n < 4; n++)
#pragma unroll
            for (int q = 0; q < 4; q++) acc[m][n][q] = 0.0f;

    for (int c = 0; c < 54; c++) {
        if (c < 52) {
            uint32_t dsts = wring_s + ((c + 2) & 3) * SLOT_B;
            const char* srcg = (const char*)g_wimg + (size_t)(c + 2) * SLOT_B;
            for (int i = t; i < 384; i += 256)
                cp_async16(dsts + i * 16, srcg + i * 16);
            cp_commit();
            cp_wait2();          // chunk c's group retired
        } else if (c == 52) {
            cp_wait1();
        } else {
            cp_wait0();
        }

        int tap = c / 6, icg = c % 6;
        int kh = tap / 3, kw = tap % 3;
        const uint4* wslot4 = (const uint4*)(wring + (c & 3) * 3072);

        uint32_t bh0[4], bh1[4];
        int rowb = kh * 130 + pxbase + kw + g;
        int icoff = icg * 16 + 2 * tig;
#pragma unroll
        for (int n = 0; n < 4; n++) {
            int off = (rowb + n * 8) * 104 + icoff;
            bh0[n] = *(const uint32_t*)(xsH + off);
            bh1[n] = *(const uint32_t*)(xsH + off + 8);
        }
#pragma unroll
        for (int m = 0; m < 6; m++) {
            uint4 av = wslot4[(ocb16 + m) * 32 + g * 4 + tig];
#pragma unroll
            for (int n = 0; n < 4; n++)
                mma16816(acc[m][n], av.x, av.y, av.z, av.w, bh0[n], bh1[n]);
        }
        if (c & 1) __syncthreads();   // slot-reuse guard (distance 4)
    }

    // ---- Fused epilogue: stage pixel-shuffled D, packed row H_s ----
    float* stage = (float*)sd;
#pragma unroll
    for (int m = 0; m < 6; m++) {
#pragma unroll
        for (int n = 0; n < 4; n++) {
#pragma unroll
            for (int q = 0; q < 4; q++) {
                int oc = (ocb16 + m) * 16 + g + 8 * (q >> 1);
                int px = pxbase + n * 8 + 2 * tig + (q & 1);
                int r2 = oc >> 1;
                int col = 2 * px + (oc & 1);
                stage[r2 * STG_STRIDE + col] = acc[m][n][q];
            }
        }
    }
    __syncthreads();

    FTw2 tw;
    make_tw2(lane, tw);
    const float sc = 1.0f / 256.0f;
#pragma unroll 1
    for (int pr = 0; pr < 6; pr++) {
        int r2a = wid * 12 + 2 * pr;
        const float* rowA = stage + r2a * STG_STRIDE;
        const float* rowB = rowA + STG_STRIDE;
        float4 a0 = *(const float4*)(rowA + 8 * lane);
        float4 a1 = *(const float4*)(rowA + 8 * lane + 4);
        float4 b0 = *(const float4*)(rowB + 8 * lane);
        float4 b1 = *(const float4*)(rowB + 8 * lane + 4);
        int cch = wid * 6 + pr;
        size_t rowImgA = ((size_t)b * 48 + cch) * 256 + 2 * h;
        ((uint4*)(g_yh + rowImgA * 256))[lane] =
            make_uint4(pack_h2(a0.x, a0.y), pack_h2(a0.z, a0.w),
                       pack_h2(a1.x, a1.y), pack_h2(a1.z, a1.w));
        ((uint4*)(g_yh + (rowImgA + 1) * 256))[lane] =
            make_uint4(pack_h2(b0.x, b0.y), pack_h2(b0.z, b0.w),
                       pack_h2(b1.x, b1.y), pack_h2(b1.z, b1.w));
        float2 d[8];
        d[0] = make_float2(a0.x, b0.x); d[1] = make_float2(a0.y, b0.y);
        d[2] = make_float2(a0.z, b0.z); d[3] = make_float2(a0.w, b0.w);
        d[4] = make_float2(a1.x, b1.x); d[5] = make_float2(a1.y, b1.y);
        d[6] = make_float2(a1.z, b1.z); d[7] = make_float2(a1.w, b1.w);
        float2 X192 = make_float2(0.f, 0.f), X64 = make_float2(0.f, 0.f);
        apply_Hs_ext(d, tw, lane, X192, X64);
        ((uint4*)(g_h + rowImgA * 256))[lane] =
            make_uint4(pack_h2(d[0].x * sc, d[1].x * sc), pack_h2(d[2].x * sc, d[3].x * sc),
                       pack_h2(d[4].x * sc, d[5].x * sc), pack_h2(d[6].x * sc, d[7].x * sc));
        ((uint4*)(g_h + (rowImgA + 1) * 256))[lane] =
            make_uint4(pack_h2(d[0].y * sc, d[1].y * sc), pack_h2(d[2].y * sc, d[3].y * sc),
                       pack_h2(d[4].y * sc, d[5].y * sc), pack_h2(d[6].y * sc, d[7].y * sc));
        if (lane == 0) {
            float2 ca = make_float2((X192.x + X64.x) * 0.5f * sc,
                                    (X192.y - X64.y) * 0.5f * sc);
            float2 inner = make_float2((X192.x - X64.x) * 0.5f * sc,
                                       (X192.y + X64.y) * 0.5f * sc);
            float2 cb = make_float2(inner.y, -inner.x);
            g_c[rowImgA] = ca;
            g_c[rowImgA + 1] = cb;
        }
    }
}

// ---------------------------------------------------------------------------
// Column pass: 64 cols/CTA (4 packed FFTs/warp), warp 0 computes W = H(c).
// ---------------------------------------------------------------------------
#define COL_SMEM (32 * 257 * 4 + 256 * 8)   // 34944

__global__ void __launch_bounds__(256, 5) col_kernel(const float* __restrict__ beta,
                                                     float* __restrict__ out) {
    extern __shared__ uint32_t sm[];
    uint32_t* tileP = sm;                    // [32][257] packed half2 / mags
    float2* Wf2 = (float2*)(sm + 32 * 257);

    int t = threadIdx.x;
    int img = blockIdx.x >> 2;
    int c0 = (blockIdx.x & 3) << 6;
    size_t ibase = (size_t)img * 65536;
    const uint32_t* hb = (const uint32_t*)g_h + ibase / 2;

    int lane = t & 31, wp = t >> 5;
    FTw2 tw;
    make_tw2(lane, tw);

    int p = t & 31, rg = t >> 5;
#pragma unroll 4
    for (int k = 0; k < 32; k++) {
        int r = rg + k * 8;
        tileP[p * 257 + ((r & 7) << 5) + (r >> 3)] = hb[r * 128 + (c0 >> 1) + p];
    }
    if (wp == 0) {
        const float sc = 1.0f / 256.0f;
        float2 d[8];
#pragma unroll
        for (int j = 0; j < 8; j++) d[j] = g_c[img * 256 + 8 * lane + j];
        apply_H(d, tw, lane);
#pragma unroll
        for (int j = 0; j < 8; j++)
            Wf2[(j << 5) | lane] = make_float2(d[j].x * sc, d[j].y * sc);
    }
    __syncthreads();

    const float sc = 1.0f / 256.0f;
#pragma unroll 1
    for (int cc = 0; cc < 4; cc++) {
        int pi = wp * 4 + cc;
        int n0 = c0 + 2 * pi;
        float2 d[8];
#pragma unroll
        for (int j = 0; j < 8; j++) d[j] = unpack_h2(tileP[pi * 257 + j * 32 + lane]);
        float2 X192 = make_float2(0.f, 0.f), X64 = make_float2(0.f, 0.f);
        apply_Hs_ext(d, tw, lane, X192, X64);
        float x192x = __shfl_sync(0xffffffffu, X192.x, 0);
        float x192y = __shfl_sync(0xffffffffu, X192.y, 0);
        float x64x  = __shfl_sync(0xffffffffu, X64.x, 0);
        float x64y  = __shfl_sync(0xffffffffu, X64.y, 0);
        float2 d0 = make_float2((x192x + x64x) * 0.5f * sc, (x192y - x64y) * 0.5f * sc);
        float2 inner = make_float2((x192x - x64x) * 0.5f * sc, (x192y + x64y) * 0.5f * sc);
        float2 d1 = make_float2(inner.y, -inner.x);
        int rot0 = n0 & 3, rot1 = (n0 + 1) & 3;
#pragma unroll
        for (int j = 0; j < 8; j++) {
            int pos = j * 32 + lane;
            float2 Wm = Wf2[pos];
            float2 w0 = rotmi(Wm, rot0);
            float2 w1 = rotmi(Wm, rot1);
            float2 cj0 = rotmi(d0, j);
            float2 cj1 = rotmi(d1, j);
            float vr0 = d[j].x * sc + cj0.x + w0.x;
            float vi0 = cj0.y + w0.y;
            float vr1 = d[j].y * sc + cj1.x + w1.x;
            float vi1 = cj1.y + w1.y;
            float m0 = fsqrt_ap(vr0 * vr0 + vi0 * vi0);
            float m1 = fsqrt_ap(vr1 * vr1 + vi1 * vi1);
            tileP[pi * 257 + pos] = pack_h2(m0, m1);
        }
    }
    __syncthreads();

    float be = *beta;
    float a0c = be;
    float a1c = 1.0f - 2.0f * be;
    int cp = t & 31, rg2 = t >> 5;
#pragma unroll 4
    for (int k = 0; k < 32; k++) {
        int r = rg2 + k * 8;
        size_t gg = ibase + (size_t)r * 256 + c0 + 2 * cp;
        float2 yf = unpack_h2(*(const uint32_t*)(g_yh + gg));
        int pos = ((r & 7) << 5) + (r >> 3);
        float2 mg = unpack_h2(tileP[cp * 257 + pos]);
        *(float2*)(out + gg) = make_float2(a0c * yf.x + a1c * mg.x,
                                           a0c * yf.y + a1c * mg.y);
    }
}

// ---------------------------------------------------------------------------
extern "C" void kernel_launch(void* const* d_in, const int* in_sizes, int n_in,
                              void* d_out, int out_size) {
    const float* x = (const float*)d_in[0];
    const float* w = (const float*)d_in[1];
    const float* beta = (const float*)d_in[2];
    float* out = (float*)d_out;

    cudaFuncSetAttribute(conv_mma_kernel, cudaFuncAttributeMaxDynamicSharedMemorySize, CONV_SMEM);
    cudaFuncSetAttribute(col_kernel, cudaFuncAttributeMaxDynamicSharedMemorySize, COL_SMEM);

    prep_kernel<<<12936, 256>>>(w, x);
    conv_mma_kernel<<<dim3(128, 8), 256, CONV_SMEM>>>();
    col_kernel<<<384 * 4, 256, COL_SMEM>>>(beta, out);
}

// round 15
// speedup vs baseline: 1.0305x; 1.0305x over previous
#include <cuda_runtime.h>
#include <cuda_fp16.h>
#include <math.h>
#include <stdint.h>

#define PI_F 3.14159265358979f

// ---------------------------------------------------------------------------
// Scratch (__device__ globals; no runtime alloc)
// ---------------------------------------------------------------------------
__device__ __half    g_yh[25165824];      // conv output fp16, pixel-shuffled (8,48,256,256)
__device__ __half    g_h[25165824];       // REAL field h = H_s(rows) fp16
__device__ __half    g_xh[12582912];      // x transposed [b][hw][ic], fp16
__device__ __half    g_wimg[165888];      // weights fp16: 54 chunks x 3072 (LDS.128 frag layout)
__device__ float2    g_c[98304];          // per (image,row): c correction scalars

// ---------------------------------------------------------------------------
// mma.sync (fp16 in, f32 acc)
// ---------------------------------------------------------------------------
__device__ __forceinline__ void mma16816(float c[4],
                                         uint32_t a0, uint32_t a1, uint32_t a2, uint32_t a3,
                                         uint32_t b0, uint32_t b1) {
    asm volatile(
        "mma.sync.aligned.m16n8k16.row.col.f32.f16.f16.f32 "
        "{%0,%1,%2,%3}, {%4,%5,%6,%7}, {%8,%9}, {%0,%1,%2,%3};"
        : "+f"(c[0]), "+f"(c[1]), "+f"(c[2]), "+f"(c[3])
        : "r"(a0), "r"(a1), "r"(a2), "r"(a3), "r"(b0), "r"(b1));
}

__device__ __forceinline__ uint32_t smem_u32(const void* p) {
    uint32_t a;
    asm("{ .reg .u64 t; cvta.to.shared.u64 t, %1; cvt.u32.u64 %0, t; }" : "=r"(a) : "l"(p));
    return a;
}
__device__ __forceinline__ void cp_async16(uint32_t dst, const void* src) {
    asm volatile("cp.async.cg.shared.global [%0], [%1], 16;" :: "r"(dst), "l"(src));
}
__device__ __forceinline__ void cp_async16z(uint32_t dst, const void* src, bool inb) {
    int sz = inb ? 16 : 0;
    asm volatile("cp.async.cg.shared.global [%0], [%1], 16, %2;" :: "r"(dst), "l"(src), "r"(sz));
}
__device__ __forceinline__ void cp_commit() { asm volatile("cp.async.commit_group;"); }
__device__ __forceinline__ void cp_wait0()  { asm volatile("cp.async.wait_group 0;"); }
__device__ __forceinline__ void cp_wait1()  { asm volatile("cp.async.wait_group 1;"); }
__device__ __forceinline__ void cp_wait2()  { asm volatile("cp.async.wait_group 2;"); }

__device__ __forceinline__ uint32_t pack_h2(float a, float b) {
    uint32_t r;
    asm("cvt.rn.f16x2.f32 %0, %1, %2;" : "=r"(r) : "f"(b), "f"(a));
    return r;
}
__device__ __forceinline__ float2 unpack_h2(uint32_t v) {
    __half2 h = *reinterpret_cast<const __half2*>(&v);
    return __half22float2(h);
}
__device__ __forceinline__ float fsqrt_ap(float x) {
    float r;
    asm("sqrt.approx.f32 %0, %1;" : "=f"(r) : "f"(x));
    return r;
}

// ---------------------------------------------------------------------------
// Warp-FFT machinery
// ---------------------------------------------------------------------------
__device__ __forceinline__ float2 cadd(float2 a, float2 b) { return make_float2(a.x + b.x, a.y + b.y); }
__device__ __forceinline__ float2 csub(float2 a, float2 b) { return make_float2(a.x - b.x, a.y - b.y); }
__device__ __forceinline__ float2 cmul(float2 a, float2 b) {
    return make_float2(a.x * b.x - a.y * b.y, a.x * b.y + a.y * b.x);
}
__device__ __forceinline__ float2 cconj(float2 a) { return make_float2(a.x, -a.y); }
__device__ __forceinline__ float2 expi(float a) {
    float s, c;
    __sincosf(a, &s, &c);
    return make_float2(c, s);
}
__device__ __forceinline__ float2 shflxc(float2 v, int m) {
    v.x = __shfl_xor_sync(0xffffffffu, v.x, m);
    v.y = __shfl_xor_sync(0xffffffffu, v.y, m);
    return v;
}
// multiply by (-i)^s
__device__ __forceinline__ float2 rotmi(float2 v, int s) {
    s &= 3;
    if (s == 0) return v;
    if (s == 1) return make_float2(v.y, -v.x);
    if (s == 2) return make_float2(-v.x, -v.y);
    return make_float2(-v.y, v.x);
}

struct FTw2 { float2 ws0, ws1, ws2, ws3, mb; };

__device__ __forceinline__ void make_tw2(int lane, FTw2& t) {
    int brl = __brev((unsigned)lane) >> 27;
    t.ws0 = expi(-PI_F * (float)(lane & 15) / 16.0f);
    t.ws1 = expi(-PI_F * (float)(lane & 7) / 8.0f);
    const float R = 0.70710678118654752f;
    int a2 = lane & 3;
    t.ws2 = (a2 == 0) ? make_float2(1.f, 0.f)
          : (a2 == 1) ? make_float2(R, -R)
          : (a2 == 2) ? make_float2(0.f, -1.f)
                      : make_float2(-R, -R);
    t.ws3 = (lane & 1) ? make_float2(0.f, -1.f) : make_float2(1.f, 0.f);
    t.mb  = expi(-2.0f * PI_F * (float)brl / 256.0f);
}

__device__ __forceinline__ void xstage_fwd(float2 d[8], int S, float2 w, int lane) {
    bool hi = (lane & S) != 0;
#pragma unroll
    for (int j = 0; j < 8; j++) {
        float2 o = shflxc(d[j], S);
        d[j] = hi ? cmul(csub(o, d[j]), w) : cadd(d[j], o);
    }
}
__device__ __forceinline__ void xstage_unity(float2 d[8], int lane) {
    bool hi = (lane & 1) != 0;
#pragma unroll
    for (int j = 0; j < 8; j++) {
        float2 o = shflxc(d[j], 1);
        d[j] = hi ? csub(o, d[j]) : cadd(d[j], o);
    }
}
__device__ __forceinline__ void xstage_inv(float2 d[8], int S, float2 wc, int lane) {
    bool hi = (lane & S) != 0;
#pragma unroll
    for (int j = 0; j < 8; j++) {
        float2 pre = hi ? cmul(d[j], wc) : d[j];
        float2 o = shflxc(pre, S);
        d[j] = hi ? csub(o, pre) : cadd(pre, o);
    }
}

__device__ __forceinline__ void fftH_front(float2 d[8], const FTw2& t, int lane) {
    xstage_fwd(d, 16, t.ws0, lane);
    xstage_fwd(d, 8,  t.ws1, lane);
    xstage_fwd(d, 4,  t.ws2, lane);
    xstage_fwd(d, 2,  t.ws3, lane);
    xstage_unity(d, lane);
    {
        float2 m = t.mb;
        d[1] = cmul(d[1], m);
#pragma unroll
        for (int j = 2; j < 8; j++) { m = cmul(m, t.mb); d[j] = cmul(d[j], m); }
    }
    const float R = 0.70710678118654752f;
    const float2 W81 = make_float2(R, -R);
    const float2 W83 = make_float2(-R, -R);
    {
        float2 u, v, tt;
        u = d[0]; v = d[4]; d[0] = cadd(u, v); d[4] = csub(u, v);
        u = d[1]; v = d[5]; d[1] = cadd(u, v); d[5] = cmul(csub(u, v), W81);
        u = d[2]; v = d[6]; d[2] = cadd(u, v); tt = csub(u, v); d[6] = make_float2(tt.y, -tt.x);
        u = d[3]; v = d[7]; d[3] = cadd(u, v); d[7] = cmul(csub(u, v), W83);
    }
#pragma unroll
    for (int gg = 0; gg < 8; gg += 4) {
        float2 u, v, tt;
        u = d[gg];     v = d[gg + 2]; d[gg] = cadd(u, v);     d[gg + 2] = csub(u, v);
        u = d[gg + 1]; v = d[gg + 3]; tt = csub(u, v);
        d[gg + 1] = cadd(u, v); d[gg + 3] = make_float2(tt.y, -tt.x);
    }
}

__device__ __forceinline__ void fftH_back(float2 d[8], const FTw2& t, int lane,
                                          bool zero192, float2* X192, float2* X64) {
    {
        float2 p = cadd(d[0], d[1]);
        float2 q = csub(d[2], d[3]);
        float2 s64 = cadd(d[2], d[3]);
        float2 r = cadd(d[4], d[5]);
        float2 s = csub(d[6], d[7]);
        if (X192 && lane == 0) { *X192 = q; *X64 = s64; }
        if (zero192 && lane == 0) q = make_float2(0.f, 0.f);
        d[0] = cadd(p, q);
        d[2] = csub(p, q);
        d[1] = make_float2(p.x + q.y, p.y - q.x);
        d[3] = make_float2(p.x - q.y, p.y + q.x);
        d[4] = cadd(r, s);
        d[6] = csub(r, s);
        d[5] = make_float2(r.x + s.y, r.y - s.x);
        d[7] = make_float2(r.x - s.y, r.y + s.x);
    }
    const float R = 0.70710678118654752f;
    const float2 W81c = make_float2(R, R);
    const float2 W83c = make_float2(-R, R);
    {
        float2 a, v;
        a = d[0]; v = d[4];                d[0] = cadd(a, v); d[4] = csub(a, v);
        a = d[1]; v = cmul(d[5], W81c);    d[1] = cadd(a, v); d[5] = csub(a, v);
        a = d[2]; { float2 bq = d[6]; v = make_float2(-bq.y, bq.x); } d[2] = cadd(a, v); d[6] = csub(a, v);
        a = d[3]; v = cmul(d[7], W83c);    d[3] = cadd(a, v); d[7] = csub(a, v);
    }
    {
        float2 mc = cconj(t.mb);
        float2 m = mc;
        d[1] = cmul(d[1], m);
#pragma unroll
        for (int j = 2; j < 8; j++) { m = cmul(m, mc); d[j] = cmul(d[j], m); }
    }
    xstage_unity(d, lane);
    xstage_inv(d, 2,  cconj(t.ws3), lane);
    xstage_inv(d, 4,  cconj(t.ws2), lane);
    xstage_inv(d, 8,  cconj(t.ws1), lane);
    xstage_inv(d, 16, cconj(t.ws0), lane);
}

__device__ __forceinline__ void apply_H(float2 d[8], const FTw2& t, int lane) {
    fftH_front(d, t, lane);
    fftH_back(d, t, lane, false, nullptr, nullptr);
}
__device__ __forceinline__ void apply_Hs_ext(float2 d[8], const FTw2& t, int lane,
                                             float2& X192, float2& X64) {
    fftH_front(d, t, lane);
    fftH_back(d, t, lane, true, &X192, &X64);
}

// ---------------------------------------------------------------------------
// Merged prep: blocks [0,648) weight fragments; [648, 12936) x transpose.
// ---------------------------------------------------------------------------
__global__ void __launch_bounds__(256) prep_kernel(const float* __restrict__ wgt,
                                                   const float* __restrict__ x) {
    __shared__ float tile[32][33];
    int t = threadIdx.x;
    int bid = blockIdx.x;
    if (bid < 648) {
        int i = bid * 256 + t;
        int e = i % 3072;
        int c = i / 3072;
        int b16 = e >> 3, h8 = e & 7;
        int tig = b16 & 3, g = (b16 >> 2) & 7, mglob = b16 >> 5;
        int ah = h8 >> 1, par = h8 & 1;
        int oc = mglob * 16 + g + 8 * (ah & 1);
        int k = ((ah >> 1) ? 8 : 0) + 2 * tig + par;
        int tap = c / 6, icg = c % 6;
        int kh = tap / 3, kw = tap % 3;
        int ic = icg * 16 + k;
        float w = wgt[((size_t)oc * 96 + ic) * 9 + kh * 3 + kw];
        g_wimg[c * 3072 + e] = __float2half(w);
        return;
    }
    int bid2 = bid - 648;
    int j = t & 31, i4 = t >> 5;
    int hw0 = (bid2 & 511) * 32;
    int ic0 = ((bid2 >> 9) % 3) * 32;
    int b = bid2 / 1536;
#pragma unroll
    for (int r = 0; r < 4; r++) {
        int ic = ic0 + i4 * 4 + r;
        tile[i4 * 4 + r][j] = x[((size_t)b * 96 + ic) * 16384 + hw0 + j];
    }
    __syncthreads();
#pragma unroll
    for (int r = 0; r < 4; r++) {
        int hwl = i4 * 4 + r;
        float v = tile[j][hwl];
        size_t idx = ((size_t)b * 16384 + hw0 + hwl) * 96 + ic0 + j;
        g_xh[idx] = __float2half(v);
    }
}

// ---------------------------------------------------------------------------
// Conv implicit GEMM + packed row-H_s epilogue.
// 4-slot weight ring, prefetch depth 2, barrier every 2 chunks.
// ---------------------------------------------------------------------------
#define XS_ELEMS 40560
#define WOFF_B 81120
#define SLOT_B 6144
#define STG_STRIDE 264
#define CONV_SMEM (WOFF_B + 4 * SLOT_B)   // 105696 >= stage 101376

__global__ void __launch_bounds__(256, 2) conv_mma_kernel() {
    extern __shared__ char sd[];
    __half* xsH = (__half*)sd;
    __half* wring = (__half*)(sd + WOFF_B);

    int t = threadIdx.x;
    int h = blockIdx.x;
    int b = blockIdx.y;
    int wid = t >> 5, lane = t & 31;
    int g = lane >> 2, tig = lane & 3;
    int ocb16 = (wid >> 2) * 6;
    int pxbase = (wid & 3) * 32;

    // G0: chunks 0,1 into slots 0,1 (768 x 16B)
    uint32_t wring_s = smem_u32(wring);
    for (int i = t; i < 768; i += 256)
        cp_async16(wring_s + i * 16, (const char*)g_wimg + i * 16);
    cp_commit();

    // G1: stage input rows with halo: [3 kh][130 ww][104 ic]
    {
        const __half* xb_h = g_xh + (size_t)b * 16384 * 96;
        uint32_t xs_s = smem_u32(xsH);
        for (int idx = t; idx < 4680; idx += 256) {
            int c16 = idx % 12;
            int ww = (idx / 12) % 130;
            int kh = idx / (12 * 130);
            int hp = h + kh - 1;
            int wp = ww - 1;
            bool inb = (hp >= 0 && hp < 128 && wp >= 0 && wp < 128);
            size_t src = inb ? (((size_t)hp * 128 + wp) * 96 + c16 * 8) : 0;
            int dst = kh * 13520 + ww * 104 + c16 * 8;
            cp_async16z(xs_s + dst * 2, xb_h + src, inb);
        }
    }
    cp_commit();
    cp_wait0();
    __syncthreads();

    float acc[6][4][4];
#pragma unroll
    for (int m = 0; m < 6; m++)
#pragma unroll
        for (int n = 0; n < 4; n++)
#pragma unroll
            for (int q = 0; q < 4; q++) acc[m][n][q] = 0.0f;

    for (int c = 0; c < 54; c++) {
        if (c < 52) {
            uint32_t dsts = wring_s + ((c + 2) & 3) * SLOT_B;
            const char* srcg = (const char*)g_wimg + (size_t)(c + 2) * SLOT_B;
            for (int i = t; i < 384; i += 256)
                cp_async16(dsts + i * 16, srcg + i * 16);
            cp_commit();
            cp_wait2();
        } else if (c == 52) {
            cp_wait1();
        } else {
            cp_wait0();
        }

        int tap = c / 6, icg = c % 6;
        int kh = tap / 3, kw = tap % 3;
        const uint4* wslot4 = (const uint4*)(wring + (c & 3) * 3072);

        uint32_t bh0[4], bh1[4];
        int rowb = kh * 130 + pxbase + kw + g;
        int icoff = icg * 16 + 2 * tig;
#pragma unroll
        for (int n = 0; n < 4; n++) {
            int off = (rowb + n * 8) * 104 + icoff;
            bh0[n] = *(const uint32_t*)(xsH + off);
            bh1[n] = *(const uint32_t*)(xsH + off + 8);
        }
#pragma unroll
        for (int m = 0; m < 6; m++) {
            uint4 av = wslot4[(ocb16 + m) * 32 + g * 4 + tig];
#pragma unroll
            for (int n = 0; n < 4; n++)
                mma16816(acc[m][n], av.x, av.y, av.z, av.w, bh0[n], bh1[n]);
        }
        if (c & 1) __syncthreads();   // slot-reuse guard (distance 4)
    }

    // ---- Fused epilogue: stage pixel-shuffled D, packed row H_s ----
    float* stage = (float*)sd;
#pragma unroll
    for (int m = 0; m < 6; m++) {
#pragma unroll
        for (int n = 0; n < 4; n++) {
#pragma unroll
            for (int q = 0; q < 4; q++) {
                int oc = (ocb16 + m) * 16 + g + 8 * (q >> 1);
                int px = pxbase + n * 8 + 2 * tig + (q & 1);
                int r2 = oc >> 1;
                int col = 2 * px + (oc & 1);
                stage[r2 * STG_STRIDE + col] = acc[m][n][q];
            }
        }
    }
    __syncthreads();

    FTw2 tw;
    make_tw2(lane, tw);
    const float sc = 1.0f / 256.0f;
#pragma unroll 1
    for (int pr = 0; pr < 6; pr++) {
        int r2a = wid * 12 + 2 * pr;
        const float* rowA = stage + r2a * STG_STRIDE;
        const float* rowB = rowA + STG_STRIDE;
        float4 a0 = *(const float4*)(rowA + 8 * lane);
        float4 a1 = *(const float4*)(rowA + 8 * lane + 4);
        float4 b0 = *(const float4*)(rowB + 8 * lane);
        float4 b1 = *(const float4*)(rowB + 8 * lane + 4);
        int cch = wid * 6 + pr;
        size_t rowImgA = ((size_t)b * 48 + cch) * 256 + 2 * h;
        ((uint4*)(g_yh + rowImgA * 256))[lane] =
            make_uint4(pack_h2(a0.x, a0.y), pack_h2(a0.z, a0.w),
                       pack_h2(a1.x, a1.y), pack_h2(a1.z, a1.w));
        ((uint4*)(g_yh + (rowImgA + 1) * 256))[lane] =
            make_uint4(pack_h2(b0.x, b0.y), pack_h2(b0.z, b0.w),
                       pack_h2(b1.x, b1.y), pack_h2(b1.z, b1.w));
        float2 d[8];
        d[0] = make_float2(a0.x, b0.x); d[1] = make_float2(a0.y, b0.y);
        d[2] = make_float2(a0.z, b0.z); d[3] = make_float2(a0.w, b0.w);
        d[4] = make_float2(a1.x, b1.x); d[5] = make_float2(a1.y, b1.y);
        d[6] = make_float2(a1.z, b1.z); d[7] = make_float2(a1.w, b1.w);
        float2 X192 = make_float2(0.f, 0.f), X64 = make_float2(0.f, 0.f);
        apply_Hs_ext(d, tw, lane, X192, X64);
        ((uint4*)(g_h + rowImgA * 256))[lane] =
            make_uint4(pack_h2(d[0].x * sc, d[1].x * sc), pack_h2(d[2].x * sc, d[3].x * sc),
                       pack_h2(d[4].x * sc, d[5].x * sc), pack_h2(d[6].x * sc, d[7].x * sc));
        ((uint4*)(g_h + (rowImgA + 1) * 256))[lane] =
            make_uint4(pack_h2(d[0].y * sc, d[1].y * sc), pack_h2(d[2].y * sc, d[3].y * sc),
                       pack_h2(d[4].y * sc, d[5].y * sc), pack_h2(d[6].y * sc, d[7].y * sc));
        if (lane == 0) {
            float2 ca = make_float2((X192.x + X64.x) * 0.5f * sc,
                                    (X192.y - X64.y) * 0.5f * sc);
            float2 inner = make_float2((X192.x - X64.x) * 0.5f * sc,
                                       (X192.y + X64.y) * 0.5f * sc);
            float2 cb = make_float2(inner.y, -inner.x);
            g_c[rowImgA] = ca;
            g_c[rowImgA + 1] = cb;
        }
    }
}

// ---------------------------------------------------------------------------
// Column pass (round-13 validated): 32 cols/CTA, warp 0 computes W = H(c).
// ---------------------------------------------------------------------------
#define COL_SMEM (16 * 257 * 4 + 256 * 8)   // 18496

__global__ void __launch_bounds__(256, 5) col_kernel(const float* __restrict__ beta,
                                                     float* __restrict__ out) {
    extern __shared__ uint32_t sm[];
    uint32_t* tileP = sm;
    float2* Wf2 = (float2*)(sm + 16 * 257);

    int t = threadIdx.x;
    int img = blockIdx.x >> 3;
    int c0 = (blockIdx.x & 7) << 5;
    size_t ibase = (size_t)img * 65536;
    const uint32_t* hb = (const uint32_t*)g_h + ibase / 2;

    int lane = t & 31, wp = t >> 5;
    FTw2 tw;
    make_tw2(lane, tw);

    int p = t & 15, rg = t >> 4;
#pragma unroll 4
    for (int k = 0; k < 16; k++) {
        int r = rg + k * 16;
        tileP[p * 257 + ((r & 7) << 5) + (r >> 3)] = hb[r * 128 + (c0 >> 1) + p];
    }
    if (wp == 0) {
        const float sc = 1.0f / 256.0f;
        float2 d[8];
#pragma unroll
        for (int j = 0; j < 8; j++) d[j] = g_c[img * 256 + 8 * lane + j];
        apply_H(d, tw, lane);
#pragma unroll
        for (int j = 0; j < 8; j++)
            Wf2[(j << 5) | lane] = make_float2(d[j].x * sc, d[j].y * sc);
    }
    __syncthreads();

    const float sc = 1.0f / 256.0f;
#pragma unroll 1
    for (int cc = 0; cc < 2; cc++) {
        int pi = wp * 2 + cc;
        int n0 = c0 + 2 * pi;
        float2 d[8];
#pragma unroll
        for (int j = 0; j < 8; j++) d[j] = unpack_h2(tileP[pi * 257 + j * 32 + lane]);
        float2 X192 = make_float2(0.f, 0.f), X64 = make_float2(0.f, 0.f);
        apply_Hs_ext(d, tw, lane, X192, X64);
        float x192x = __shfl_sync(0xffffffffu, X192.x, 0);
        float x192y = __shfl_sync(0xffffffffu, X192.y, 0);
        float x64x  = __shfl_sync(0xffffffffu, X64.x, 0);
        float x64y  = __shfl_sync(0xffffffffu, X64.y, 0);
        float2 d0 = make_float2((x192x + x64x) * 0.5f * sc, (x192y - x64y) * 0.5f * sc);
        float2 inner = make_float2((x192x - x64x) * 0.5f * sc, (x192y + x64y) * 0.5f * sc);
        float2 d1 = make_float2(inner.y, -inner.x);
        int rot0 = n0 & 3, rot1 = (n0 + 1) & 3;
#pragma unroll
        for (int j = 0; j < 8; j++) {
            int pos = j * 32 + lane;
            float2 Wm = Wf2[pos];
            float2 w0 = rotmi(Wm, rot0);
            float2 w1 = rotmi(Wm, rot1);
            float2 cj0 = rotmi(d0, j);
            float2 cj1 = rotmi(d1, j);
            float vr0 = d[j].x * sc + cj0.x + w0.x;
            float vi0 = cj0.y + w0.y;
            float vr1 = d[j].y * sc + cj1.x + w1.x;
            float vi1 = cj1.y + w1.y;
            float m0 = fsqrt_ap(vr0 * vr0 + vi0 * vi0);
            float m1 = fsqrt_ap(vr1 * vr1 + vi1 * vi1);
            tileP[pi * 257 + pos] = pack_h2(m0, m1);
        }
    }
    __syncthreads();

    float be = *beta;
    float a0c = be;
    float a1c = 1.0f - 2.0f * be;
    int cp = t & 15, rg2 = t >> 4;
#pragma unroll 4
    for (int k = 0; k < 16; k++) {
        int r = rg2 + k * 16;
        size_t gg = ibase + (size_t)r * 256 + c0 + 2 * cp;
        float2 yf = unpack_h2(*(const uint32_t*)(g_yh + gg));
        int pos = ((r & 7) << 5) + (r >> 3);
        float2 mg = unpack_h2(tileP[cp * 257 + pos]);
        *(float2*)(out + gg) = make_float2(a0c * yf.x + a1c * mg.x,
                                           a0c * yf.y + a1c * mg.y);
    }
}

// ---------------------------------------------------------------------------
extern "C" void kernel_launch(void* const* d_in, const int* in_sizes, int n_in,
                              void* d_out, int out_size) {
    const float* x = (const float*)d_in[0];
    const float* w = (const float*)d_in[1];
    const float* beta = (const float*)d_in[2];
    float* out = (float*)d_out;

    cudaFuncSetAttribute(conv_mma_kernel, cudaFuncAttributeMaxDynamicSharedMemorySize, CONV_SMEM);
    cudaFuncSetAttribute(col_kernel, cudaFuncAttributeMaxDynamicSharedMemorySize, COL_SMEM);

    prep_kernel<<<12936, 256>>>(w, x);
    conv_mma_kernel<<<dim3(128, 8), 256, CONV_SMEM>>>();
    col_kernel<<<384 * 8, 256, COL_SMEM>>>(beta, out);
}

// round 16
// speedup vs baseline: 1.0654x; 1.0339x over previous
#include <cuda_runtime.h>
#include <cuda_fp16.h>
#include <math.h>
#include <stdint.h>

#define PI_F 3.14159265358979f

// ---------------------------------------------------------------------------
// Scratch (__device__ globals; no runtime alloc)
// ---------------------------------------------------------------------------
__device__ __half    g_yh[25165824];      // conv output fp16, pixel-shuffled (8,48,256,256)
__device__ __half    g_h[25165824];       // REAL field h = H_s(rows) fp16
__device__ __half    g_xh[12582912];      // x transposed [b][hw][ic], fp16
__device__ __half    g_wimg[165888];      // weights fp16: 54 chunks x 3072 (LDS.128 frag layout)
__device__ float2    g_c[98304];          // per (image,row): c correction scalars

// ---------------------------------------------------------------------------
// mma.sync (fp16 in, f32 acc)
// ---------------------------------------------------------------------------
__device__ __forceinline__ void mma16816(float c[4],
                                         uint32_t a0, uint32_t a1, uint32_t a2, uint32_t a3,
                                         uint32_t b0, uint32_t b1) {
    asm volatile(
        "mma.sync.aligned.m16n8k16.row.col.f32.f16.f16.f32 "
        "{%0,%1,%2,%3}, {%4,%5,%6,%7}, {%8,%9}, {%0,%1,%2,%3};"
        : "+f"(c[0]), "+f"(c[1]), "+f"(c[2]), "+f"(c[3])
        : "r"(a0), "r"(a1), "r"(a2), "r"(a3), "r"(b0), "r"(b1));
}

__device__ __forceinline__ uint32_t smem_u32(const void* p) {
    uint32_t a;
    asm("{ .reg .u64 t; cvta.to.shared.u64 t, %1; cvt.u32.u64 %0, t; }" : "=r"(a) : "l"(p));
    return a;
}
__device__ __forceinline__ void cp_async16(uint32_t dst, const void* src) {
    asm volatile("cp.async.cg.shared.global [%0], [%1], 16;" :: "r"(dst), "l"(src));
}
__device__ __forceinline__ void cp_async16z(uint32_t dst, const void* src, bool inb) {
    int sz = inb ? 16 : 0;
    asm volatile("cp.async.cg.shared.global [%0], [%1], 16, %2;" :: "r"(dst), "l"(src), "r"(sz));
}
__device__ __forceinline__ void cp_commit() { asm volatile("cp.async.commit_group;"); }
__device__ __forceinline__ void cp_wait0()  { asm volatile("cp.async.wait_group 0;"); }
__device__ __forceinline__ void cp_wait1()  { asm volatile("cp.async.wait_group 1;"); }
__device__ __forceinline__ void cp_wait2()  { asm volatile("cp.async.wait_group 2;"); }

__device__ __forceinline__ uint32_t pack_h2(float a, float b) {
    uint32_t r;
    asm("cvt.rn.f16x2.f32 %0, %1, %2;" : "=r"(r) : "f"(b), "f"(a));
    return r;
}
__device__ __forceinline__ float2 unpack_h2(uint32_t v) {
    __half2 h = *reinterpret_cast<const __half2*>(&v);
    return __half22float2(h);
}
__device__ __forceinline__ float fsqrt_ap(float x) {
    float r;
    asm("sqrt.approx.f32 %0, %1;" : "=f"(r) : "f"(x));
    return r;
}

// ---------------------------------------------------------------------------
// Warp-FFT machinery
// ---------------------------------------------------------------------------
__device__ __forceinline__ float2 cadd(float2 a, float2 b) { return make_float2(a.x + b.x, a.y + b.y); }
__device__ __forceinline__ float2 csub(float2 a, float2 b) { return make_float2(a.x - b.x, a.y - b.y); }
__device__ __forceinline__ float2 cmul(float2 a, float2 b) {
    return make_float2(a.x * b.x - a.y * b.y, a.x * b.y + a.y * b.x);
}
__device__ __forceinline__ float2 cconj(float2 a) { return make_float2(a.x, -a.y); }
__device__ __forceinline__ float2 expi(float a) {
    float s, c;
    __sincosf(a, &s, &c);
    return make_float2(c, s);
}
__device__ __forceinline__ float2 shflxc(float2 v, int m) {
    v.x = __shfl_xor_sync(0xffffffffu, v.x, m);
    v.y = __shfl_xor_sync(0xffffffffu, v.y, m);
    return v;
}
// multiply by (-i)^s
__device__ __forceinline__ float2 rotmi(float2 v, int s) {
    s &= 3;
    if (s == 0) return v;
    if (s == 1) return make_float2(v.y, -v.x);
    if (s == 2) return make_float2(-v.x, -v.y);
    return make_float2(-v.y, v.x);
}

struct FTw2 { float2 ws0, ws1, ws2, ws3, mb; };

__device__ __forceinline__ void make_tw2(int lane, FTw2& t) {
    int brl = __brev((unsigned)lane) >> 27;
    t.ws0 = expi(-PI_F * (float)(lane & 15) / 16.0f);
    t.ws1 = expi(-PI_F * (float)(lane & 7) / 8.0f);
    const float R = 0.70710678118654752f;
    int a2 = lane & 3;
    t.ws2 = (a2 == 0) ? make_float2(1.f, 0.f)
          : (a2 == 1) ? make_float2(R, -R)
          : (a2 == 2) ? make_float2(0.f, -1.f)
                      : make_float2(-R, -R);
    t.ws3 = (lane & 1) ? make_float2(0.f, -1.f) : make_float2(1.f, 0.f);
    t.mb  = expi(-2.0f * PI_F * (float)brl / 256.0f);
}

__device__ __forceinline__ void xstage_fwd(float2 d[8], int S, float2 w, int lane) {
    bool hi = (lane & S) != 0;
#pragma unroll
    for (int j = 0; j < 8; j++) {
        float2 o = shflxc(d[j], S);
        d[j] = hi ? cmul(csub(o, d[j]), w) : cadd(d[j], o);
    }
}
__device__ __forceinline__ void xstage_unity(float2 d[8], int lane) {
    bool hi = (lane & 1) != 0;
#pragma unroll
    for (int j = 0; j < 8; j++) {
        float2 o = shflxc(d[j], 1);
        d[j] = hi ? csub(o, d[j]) : cadd(d[j], o);
    }
}
__device__ __forceinline__ void xstage_inv(float2 d[8], int S, float2 wc, int lane) {
    bool hi = (lane & S) != 0;
#pragma unroll
    for (int j = 0; j < 8; j++) {
        float2 pre = hi ? cmul(d[j], wc) : d[j];
        float2 o = shflxc(pre, S);
        d[j] = hi ? csub(o, pre) : cadd(pre, o);
    }
}

// mid twiddles (incremental powers)
__device__ __forceinline__ void mid_tw(float2 d[8], float2 base) {
    float2 m = base;
    d[1] = cmul(d[1], m);
#pragma unroll
    for (int j = 2; j < 8; j++) { m = cmul(m, base); d[j] = cmul(d[j], m); }
}

// forward in-register radix-8 (S4 + S2)
__device__ __forceinline__ void radix8_fwd(float2 d[8]) {
    const float R = 0.70710678118654752f;
    const float2 W81 = make_float2(R, -R);
    const float2 W83 = make_float2(-R, -R);
    {
        float2 u, v, tt;
        u = d[0]; v = d[4]; d[0] = cadd(u, v); d[4] = csub(u, v);
        u = d[1]; v = d[5]; d[1] = cadd(u, v); d[5] = cmul(csub(u, v), W81);
        u = d[2]; v = d[6]; d[2] = cadd(u, v); tt = csub(u, v); d[6] = make_float2(tt.y, -tt.x);
        u = d[3]; v = d[7]; d[3] = cadd(u, v); d[7] = cmul(csub(u, v), W83);
    }
#pragma unroll
    for (int gg = 0; gg < 8; gg += 4) {
        float2 u, v, tt;
        u = d[gg];     v = d[gg + 2]; d[gg] = cadd(u, v);     d[gg + 2] = csub(u, v);
        u = d[gg + 1]; v = d[gg + 3]; tt = csub(u, v);
        d[gg + 1] = cadd(u, v); d[gg + 3] = make_float2(tt.y, -tt.x);
    }
}

// fold (pruned fwd S1 + mask + folded inv S1,S2) + inverse radix S4
__device__ __forceinline__ void fold_inv4(float2 d[8], int lane,
                                          bool zero192, float2* X192, float2* X64) {
    {
        float2 p = cadd(d[0], d[1]);
        float2 q = csub(d[2], d[3]);
        float2 s64 = cadd(d[2], d[3]);
        float2 r = cadd(d[4], d[5]);
        float2 s = csub(d[6], d[7]);
        if (X192 && lane == 0) { *X192 = q; *X64 = s64; }
        if (zero192 && lane == 0) q = make_float2(0.f, 0.f);
        d[0] = cadd(p, q);
        d[2] = csub(p, q);
        d[1] = make_float2(p.x + q.y, p.y - q.x);
        d[3] = make_float2(p.x - q.y, p.y + q.x);
        d[4] = cadd(r, s);
        d[6] = csub(r, s);
        d[5] = make_float2(r.x + s.y, r.y - s.x);
        d[7] = make_float2(r.x - s.y, r.y + s.x);
    }
    const float R = 0.70710678118654752f;
    const float2 W81c = make_float2(R, R);
    const float2 W83c = make_float2(-R, R);
    {
        float2 a, v;
        a = d[0]; v = d[4];                d[0] = cadd(a, v); d[4] = csub(a, v);
        a = d[1]; v = cmul(d[5], W81c);    d[1] = cadd(a, v); d[5] = csub(a, v);
        a = d[2]; { float2 bq = d[6]; v = make_float2(-bq.y, bq.x); } d[2] = cadd(a, v); d[6] = csub(a, v);
        a = d[3]; v = cmul(d[7], W83c);    d[3] = cadd(a, v); d[7] = csub(a, v);
    }
}

__device__ __forceinline__ void fftH_front(float2 d[8], const FTw2& t, int lane) {
    xstage_fwd(d, 16, t.ws0, lane);
    xstage_fwd(d, 8,  t.ws1, lane);
    xstage_fwd(d, 4,  t.ws2, lane);
    xstage_fwd(d, 2,  t.ws3, lane);
    xstage_unity(d, lane);
    mid_tw(d, t.mb);
    radix8_fwd(d);
}

__device__ __forceinline__ void fftH_back(float2 d[8], const FTw2& t, int lane,
                                          bool zero192, float2* X192, float2* X64) {
    fold_inv4(d, lane, zero192, X192, X64);
    mid_tw(d, cconj(t.mb));
    xstage_unity(d, lane);
    xstage_inv(d, 2,  cconj(t.ws3), lane);
    xstage_inv(d, 4,  cconj(t.ws2), lane);
    xstage_inv(d, 8,  cconj(t.ws1), lane);
    xstage_inv(d, 16, cconj(t.ws0), lane);
}

__device__ __forceinline__ void apply_Hs_ext(float2 d[8], const FTw2& t, int lane,
                                             float2& X192, float2& X64) {
    fftH_front(d, t, lane);
    fftH_back(d, t, lane, true, &X192, &X64);
}

// ---- Register-lean H for col kernel: twiddles rematerialized from e7 ----
__device__ __forceinline__ void colH(float2 d[8], float2 e7, float2 mb, int lane,
                                     bool zero192, float2* X192, float2* X64) {
    float2 e14 = cmul(e7, e7);                          // expi(-pi(l&7)/8)
    xstage_fwd(d, 16, (lane & 8) ? make_float2(e7.y, -e7.x) : e7, lane);
    xstage_fwd(d, 8, e14, lane);
    {
        float2 e28 = cmul(e14, e14);                    // expi(-pi(l&7)/4)
        xstage_fwd(d, 4, (lane & 4) ? make_float2(-e28.x, -e28.y) : e28, lane);
    }
    xstage_fwd(d, 2, (lane & 1) ? make_float2(0.f, -1.f) : make_float2(1.f, 0.f), lane);
    xstage_unity(d, lane);
    mid_tw(d, mb);
    radix8_fwd(d);
    fold_inv4(d, lane, zero192, X192, X64);
    mid_tw(d, cconj(mb));
    xstage_unity(d, lane);
    xstage_inv(d, 2, (lane & 1) ? make_float2(0.f, 1.f) : make_float2(1.f, 0.f), lane);
    {
        float2 e28 = cmul(e14, e14);
        xstage_inv(d, 4, (lane & 4) ? make_float2(-e28.x, e28.y) : make_float2(e28.x, -e28.y), lane);
    }
    xstage_inv(d, 8, cconj(e14), lane);
    xstage_inv(d, 16, (lane & 8) ? make_float2(e7.y, e7.x) : cconj(e7), lane);
}

// ---------------------------------------------------------------------------
// Merged prep: blocks [0,648) weight fragments; [648, 12936) x transpose.
// ---------------------------------------------------------------------------
__global__ void __launch_bounds__(256) prep_kernel(const float* __restrict__ wgt,
                                                   const float* __restrict__ x) {
    __shared__ float tile[32][33];
    int t = threadIdx.x;
    int bid = blockIdx.x;
    if (bid < 648) {
        int i = bid * 256 + t;
        int e = i % 3072;
        int c = i / 3072;
        int b16 = e >> 3, h8 = e & 7;
        int tig = b16 & 3, g = (b16 >> 2) & 7, mglob = b16 >> 5;
        int ah = h8 >> 1, par = h8 & 1;
        int oc = mglob * 16 + g + 8 * (ah & 1);
        int k = ((ah >> 1) ? 8 : 0) + 2 * tig + par;
        int tap = c / 6, icg = c % 6;
        int kh = tap / 3, kw = tap % 3;
        int ic = icg * 16 + k;
        float w = wgt[((size_t)oc * 96 + ic) * 9 + kh * 3 + kw];
        g_wimg[c * 3072 + e] = __float2half(w);
        return;
    }
    int bid2 = bid - 648;
    int j = t & 31, i4 = t >> 5;
    int hw0 = (bid2 & 511) * 32;
    int ic0 = ((bid2 >> 9) % 3) * 32;
    int b = bid2 / 1536;
#pragma unroll
    for (int r = 0; r < 4; r++) {
        int ic = ic0 + i4 * 4 + r;
        tile[i4 * 4 + r][j] = x[((size_t)b * 96 + ic) * 16384 + hw0 + j];
    }
    __syncthreads();
#pragma unroll
    for (int r = 0; r < 4; r++) {
        int hwl = i4 * 4 + r;
        float v = tile[j][hwl];
        size_t idx = ((size_t)b * 16384 + hw0 + hwl) * 96 + ic0 + j;
        g_xh[idx] = __float2half(v);
    }
}

// ---------------------------------------------------------------------------
// Conv implicit GEMM + packed row-H_s epilogue (validated round-15 config).
// ---------------------------------------------------------------------------
#define XS_ELEMS 40560
#define WOFF_B 81120
#define SLOT_B 6144
#define STG_STRIDE 264
#define CONV_SMEM (WOFF_B + 4 * SLOT_B)   // 105696 >= stage 101376

__global__ void __launch_bounds__(256, 2) conv_mma_kernel() {
    extern __shared__ char sd[];
    __half* xsH = (__half*)sd;
    __half* wring = (__half*)(sd + WOFF_B);

    int t = threadIdx.x;
    int h = blockIdx.x;
    int b = blockIdx.y;
    int wid = t >> 5, lane = t & 31;
    int g = lane >> 2, tig = lane & 3;
    int ocb16 = (wid >> 2) * 6;
    int pxbase = (wid & 3) * 32;

    uint32_t wring_s = smem_u32(wring);
    for (int i = t; i < 768; i += 256)
        cp_async16(wring_s + i * 16, (const char*)g_wimg + i * 16);
    cp_commit();

    {
        const __half* xb_h = g_xh + (size_t)b * 16384 * 96;
        uint32_t xs_s = smem_u32(xsH);
        for (int idx = t; idx < 4680; idx += 256) {
            int c16 = idx % 12;
            int ww = (idx / 12) % 130;
            int kh = idx / (12 * 130);
            int hp = h + kh - 1;
            int wp = ww - 1;
            bool inb = (hp >= 0 && hp < 128 && wp >= 0 && wp < 128);
            size_t src = inb ? (((size_t)hp * 128 + wp) * 96 + c16 * 8) : 0;
            int dst = kh * 13520 + ww * 104 + c16 * 8;
            cp_async16z(xs_s + dst * 2, xb_h + src, inb);
        }
    }
    cp_commit();
    cp_wait0();
    __syncthreads();

    float acc[6][4][4];
#pragma unroll
    for (int m = 0; m < 6; m++)
#pragma unroll
        for (int n = 0; n < 4; n++)
#pragma unroll
            for (int q = 0; q < 4; q++) acc[m][n][q] = 0.0f;

    for (int c = 0; c < 54; c++) {
        if (c < 52) {
            uint32_t dsts = wring_s + ((c + 2) & 3) * SLOT_B;
            const char* srcg = (const char*)g_wimg + (size_t)(c + 2) * SLOT_B;
            for (int i = t; i < 384; i += 256)
                cp_async16(dsts + i * 16, srcg + i * 16);
            cp_commit();
            cp_wait2();
        } else if (c == 52) {
            cp_wait1();
        } else {
            cp_wait0();
        }

        int tap = c / 6, icg = c % 6;
        int kh = tap / 3, kw = tap % 3;
        const uint4* wslot4 = (const uint4*)(wring + (c & 3) * 3072);

        uint32_t bh0[4], bh1[4];
        int rowb = kh * 130 + pxbase + kw + g;
        int icoff = icg * 16 + 2 * tig;
#pragma unroll
        for (int n = 0; n < 4; n++) {
            int off = (rowb + n * 8) * 104 + icoff;
            bh0[n] = *(const uint32_t*)(xsH + off);
            bh1[n] = *(const uint32_t*)(xsH + off + 8);
        }
#pragma unroll
        for (int m = 0; m < 6; m++) {
            uint4 av = wslot4[(ocb16 + m) * 32 + g * 4 + tig];
#pragma unroll
            for (int n = 0; n < 4; n++)
                mma16816(acc[m][n], av.x, av.y, av.z, av.w, bh0[n], bh1[n]);
        }
        if (c & 1) __syncthreads();   // slot-reuse guard (distance 4)
    }

    // ---- Fused epilogue: stage pixel-shuffled D, packed row H_s ----
    float* stage = (float*)sd;
#pragma unroll
    for (int m = 0; m < 6; m++) {
#pragma unroll
        for (int n = 0; n < 4; n++) {
#pragma unroll
            for (int q = 0; q < 4; q++) {
                int oc = (ocb16 + m) * 16 + g + 8 * (q >> 1);
                int px = pxbase + n * 8 + 2 * tig + (q & 1);
                int r2 = oc >> 1;
                int col = 2 * px + (oc & 1);
                stage[r2 * STG_STRIDE + col] = acc[m][n][q];
            }
        }
    }
    __syncthreads();

    FTw2 tw;
    make_tw2(lane, tw);
    const float sc = 1.0f / 256.0f;
#pragma unroll 1
    for (int pr = 0; pr < 6; pr++) {
        int r2a = wid * 12 + 2 * pr;
        const float* rowA = stage + r2a * STG_STRIDE;
        const float* rowB = rowA + STG_STRIDE;
        float4 a0 = *(const float4*)(rowA + 8 * lane);
        float4 a1 = *(const float4*)(rowA + 8 * lane + 4);
        float4 b0 = *(const float4*)(rowB + 8 * lane);
        float4 b1 = *(const float4*)(rowB + 8 * lane + 4);
        int cch = wid * 6 + pr;
        size_t rowImgA = ((size_t)b * 48 + cch) * 256 + 2 * h;
        ((uint4*)(g_yh + rowImgA * 256))[lane] =
            make_uint4(pack_h2(a0.x, a0.y), pack_h2(a0.z, a0.w),
                       pack_h2(a1.x, a1.y), pack_h2(a1.z, a1.w));
        ((uint4*)(g_yh + (rowImgA + 1) * 256))[lane] =
            make_uint4(pack_h2(b0.x, b0.y), pack_h2(b0.z, b0.w),
                       pack_h2(b1.x, b1.y), pack_h2(b1.z, b1.w));
        float2 d[8];
        d[0] = make_float2(a0.x, b0.x); d[1] = make_float2(a0.y, b0.y);
        d[2] = make_float2(a0.z, b0.z); d[3] = make_float2(a0.w, b0.w);
        d[4] = make_float2(a1.x, b1.x); d[5] = make_float2(a1.y, b1.y);
        d[6] = make_float2(a1.z, b1.z); d[7] = make_float2(a1.w, b1.w);
        float2 X192 = make_float2(0.f, 0.f), X64 = make_float2(0.f, 0.f);
        apply_Hs_ext(d, tw, lane, X192, X64);
        ((uint4*)(g_h + rowImgA * 256))[lane] =
            make_uint4(pack_h2(d[0].x * sc, d[1].x * sc), pack_h2(d[2].x * sc, d[3].x * sc),
                       pack_h2(d[4].x * sc, d[5].x * sc), pack_h2(d[6].x * sc, d[7].x * sc));
        ((uint4*)(g_h + (rowImgA + 1) * 256))[lane] =
            make_uint4(pack_h2(d[0].y * sc, d[1].y * sc), pack_h2(d[2].y * sc, d[3].y * sc),
                       pack_h2(d[4].y * sc, d[5].y * sc), pack_h2(d[6].y * sc, d[7].y * sc));
        if (lane == 0) {
            float2 ca = make_float2((X192.x + X64.x) * 0.5f * sc,
                                    (X192.y - X64.y) * 0.5f * sc);
            float2 inner = make_float2((X192.x - X64.x) * 0.5f * sc,
                                       (X192.y + X64.y) * 0.5f * sc);
            float2 cb = make_float2(inner.y, -inner.x);
            g_c[rowImgA] = ca;
            g_c[rowImgA + 1] = cb;
        }
    }
}

// ---------------------------------------------------------------------------
// Column pass: 32 cols/CTA, lean twiddles, 6 CTAs/SM target.
// ---------------------------------------------------------------------------
#define COL_SMEM (16 * 257 * 4 + 256 * 8)   // 18496

__global__ void __launch_bounds__(256, 6) col_kernel(const float* __restrict__ beta,
                                                     float* __restrict__ out) {
    extern __shared__ uint32_t sm[];
    uint32_t* tileP = sm;
    float2* Wf2 = (float2*)(sm + 16 * 257);

    int t = threadIdx.x;
    int img = blockIdx.x >> 3;
    int c0 = (blockIdx.x & 7) << 5;
    size_t ibase = (size_t)img * 65536;
    const uint32_t* hb = (const uint32_t*)g_h + ibase / 2;

    int lane = t & 31, wp = t >> 5;
    float2 e7 = expi(-PI_F * (float)(lane & 7) / 16.0f);
    float2 mb = expi(-2.0f * PI_F * (float)(__brev((unsigned)lane) >> 27) / 256.0f);

    int p = t & 15, rg = t >> 4;
#pragma unroll 4
    for (int k = 0; k < 16; k++) {
        int r = rg + k * 16;
        tileP[p * 257 + ((r & 7) << 5) + (r >> 3)] = hb[r * 128 + (c0 >> 1) + p];
    }
    if (wp == 0) {
        const float sc = 1.0f / 256.0f;
        float2 d[8];
#pragma unroll
        for (int j = 0; j < 8; j++) d[j] = g_c[img * 256 + 8 * lane + j];
        colH(d, e7, mb, lane, false, nullptr, nullptr);
#pragma unroll
        for (int j = 0; j < 8; j++)
            Wf2[(j << 5) | lane] = make_float2(d[j].x * sc, d[j].y * sc);
    }
    __syncthreads();

    const float sc = 1.0f / 256.0f;
#pragma unroll 1
    for (int cc = 0; cc < 2; cc++) {
        int pi = wp * 2 + cc;
        int n0 = c0 + 2 * pi;
        float2 d[8];
#pragma unroll
        for (int j = 0; j < 8; j++) d[j] = unpack_h2(tileP[pi * 257 + j * 32 + lane]);
        float2 X192 = make_float2(0.f, 0.f), X64 = make_float2(0.f, 0.f);
        colH(d, e7, mb, lane, true, &X192, &X64);
        float x192x = __shfl_sync(0xffffffffu, X192.x, 0);
        float x192y = __shfl_sync(0xffffffffu, X192.y, 0);
        float x64x  = __shfl_sync(0xffffffffu, X64.x, 0);
        float x64y  = __shfl_sync(0xffffffffu, X64.y, 0);
        float2 d0 = make_float2((x192x + x64x) * 0.5f * sc, (x192y - x64y) * 0.5f * sc);
        float2 inner = make_float2((x192x - x64x) * 0.5f * sc, (x192y + x64y) * 0.5f * sc);
        float2 d1 = make_float2(inner.y, -inner.x);
        int rot0 = n0 & 3, rot1 = (n0 + 1) & 3;
#pragma unroll
        for (int j = 0; j < 8; j++) {
            int pos = j * 32 + lane;
            float2 Wm = Wf2[pos];
            float2 w0 = rotmi(Wm, rot0);
            float2 w1 = rotmi(Wm, rot1);
            float2 cj0 = rotmi(d0, j);
            float2 cj1 = rotmi(d1, j);
            float vr0 = d[j].x * sc + cj0.x + w0.x;
            float vi0 = cj0.y + w0.y;
            float vr1 = d[j].y * sc + cj1.x + w1.x;
            float vi1 = cj1.y + w1.y;
            float m0 = fsqrt_ap(vr0 * vr0 + vi0 * vi0);
            float m1 = fsqrt_ap(vr1 * vr1 + vi1 * vi1);
            tileP[pi * 257 + pos] = pack_h2(m0, m1);
        }
    }
    __syncthreads();

    float be = *beta;
    float a0c = be;
    float a1c = 1.0f - 2.0f * be;
    int cp4 = t & 7, rg2 = t >> 3;
#pragma unroll 4
    for (int k = 0; k < 8; k++) {
        int r = rg2 + k * 32;
        size_t gg = ibase + (size_t)r * 256 + c0 + 4 * cp4;
        uint2 yv = *(const uint2*)(g_yh + gg);
        float2 y01 = unpack_h2(yv.x);
        float2 y23 = unpack_h2(yv.y);
        int pos = ((r & 7) << 5) + (r >> 3);
        float2 mgA = unpack_h2(tileP[(2 * cp4) * 257 + pos]);
        float2 mgB = unpack_h2(tileP[(2 * cp4 + 1) * 257 + pos]);
        float4 o;
        o.x = a0c * y01.x + a1c * mgA.x;
        o.y = a0c * y01.y + a1c * mgA.y;
        o.z = a0c * y23.x + a1c * mgB.x;
        o.w = a0c * y23.y + a1c * mgB.y;
        *(float4*)(out + gg) = o;
    }
}

// ---------------------------------------------------------------------------
extern "C" void kernel_launch(void* const* d_in, const int* in_sizes, int n_in,
                              void* d_out, int out_size) {
    const float* x = (const float*)d_in[0];
    const float* w = (const float*)d_in[1];
    const float* beta = (const float*)d_in[2];
    float* out = (float*)d_out;

    cudaFuncSetAttribute(conv_mma_kernel, cudaFuncAttributeMaxDynamicSharedMemorySize, CONV_SMEM);
    cudaFuncSetAttribute(col_kernel, cudaFuncAttributeMaxDynamicSharedMemorySize, COL_SMEM);

    prep_kernel<<<12936, 256>>>(w, x);
    conv_mma_kernel<<<dim3(128, 8), 256, CONV_SMEM>>>();
    col_kernel<<<384 * 8, 256, COL_SMEM>>>(beta, out);
}